// round 13
// baseline (speedup 1.0000x reference)
#include <cuda_runtime.h>
#include <math.h>
#include <stdint.h>

#define CC   512
#define NN1  8192
#define NN2  131072
#define NTOT 139265
#define EE   1000000
#define KK1  820
#define KK2  3280
#define MM   4101

// output layout (float32, tuple concatenated)
#define OFF_XPOOL 0ULL
#define OFF_A     2099712ULL
#define OFF_BATCH 18917913ULL
#define OFF_CLUST 18922014ULL
#define OFF_NNT   19061279ULL
#define OFF_NTREE 19065380ULL
#define OFF_FIT   19069481ULL
#define OFF_NEWXY 19208746ULL

// ---------------- device scratch ----------------
__device__ float g_f1[NN1];
__device__ float g_f2[NN2];
__device__ int   g_rank[NN1];
__device__ float g_thr[KK1 * 3];
__device__ int   g_cluster1[NN1];
__device__ int   g_parents[NN2];
__device__ int   g_counts1[KK1];
__device__ int   g_starts1[KK1];
__device__ int   g_gmembers[NN2];
__device__ int   g_cluster[NTOT];
__device__ int   g_countsM[MM];
__device__ int   g_startsM[MM];
__device__ int   g_cmembers[NTOT];
__device__ int   g_minTree = 0x7fffffff;   // persistent: atomicMin idempotent across replays

__device__ __forceinline__ unsigned int f2ord(float f) {
    unsigned int u = __float_as_uint(f);
    return (u & 0x80000000u) ? ~u : (u | 0x80000000u);
}

__device__ __forceinline__ void dep_sync() {
#if __CUDA_ARCH__ >= 900
    cudaGridDependencySynchronize();
#endif
}

// ---------------- f1: 8192 fitness rows (2 rows/warp) + zero counters + tree-min
__global__ void f1_kernel(const float* __restrict__ x,
                          const float* __restrict__ w1,
                          const int* __restrict__ tree) {
    int gid = blockIdx.x * blockDim.x + threadIdx.x;   // 512 blocks * 256
    if (gid < NN1) g_rank[gid] = 0;
    if (gid < KK1) g_counts1[gid] = 0;
    if (gid < MM)  g_countsM[gid] = (gid == 0) ? 1 : 0;
    if (gid == 0)  g_cluster[0] = 0;
    if (blockIdx.x < 64) {
        __shared__ int smin[256];
        int v = 0x7fffffff;
        for (int i = blockIdx.x * 256 + threadIdx.x; i < NN2; i += 64 * 256)
            v = min(v, tree[1 + NN1 + i]);
        smin[threadIdx.x] = v;
        __syncthreads();
        for (int off = 128; off; off >>= 1) {
            if (threadIdx.x < off) smin[threadIdx.x] = min(smin[threadIdx.x], smin[threadIdx.x + off]);
            __syncthreads();
        }
        if (threadIdx.x == 0) atomicMin(&g_minTree, smin[0]);
        __syncthreads();
    }
    int warp = gid >> 5;
    int lane = threadIdx.x & 31;
    int r0 = warp * 2;
    if (r0 >= NN1) return;
    const float4* x0 = (const float4*)(x + (size_t)(1 + r0) * CC);
    const float4* x1 = (const float4*)(x + (size_t)(2 + r0) * CC);
    const float4* wr = (const float4*)w1;
    float4 a0[4], a1[4];
#pragma unroll
    for (int k = 0; k < 4; k++) a0[k] = x0[lane + 32 * k];
#pragma unroll
    for (int k = 0; k < 4; k++) a1[k] = x1[lane + 32 * k];
    float s0 = 0.f, s1 = 0.f, wsum = 0.f;
#pragma unroll
    for (int k = 0; k < 4; k++) {
        float4 b = wr[lane + 32 * k];
        s0 += a0[k].x * b.x + a0[k].y * b.y + a0[k].z * b.z + a0[k].w * b.w;
        s1 += a1[k].x * b.x + a1[k].y * b.y + a1[k].z * b.z + a1[k].w * b.w;
        wsum += b.x * b.x + b.y * b.y + b.z * b.z + b.w * b.w;
    }
    for (int off = 16; off; off >>= 1) {
        s0   += __shfl_xor_sync(0xffffffffu, s0, off);
        s1   += __shfl_xor_sync(0xffffffffu, s1, off);
        wsum += __shfl_xor_sync(0xffffffffu, wsum, off);
    }
    if (lane == 0) {
        float nrm = sqrtf(wsum);
        g_f1[r0]     = tanhf(s0 / nrm);
        g_f1[r0 + 1] = tanhf(s1 / nrm);
    }
}

// ---------------- f2: 131072 fitness rows, 2 rows per warp
__global__ void f2_kernel(const float* __restrict__ x, const float* __restrict__ w2) {
    int warp = (blockIdx.x * blockDim.x + threadIdx.x) >> 5;
    int lane = threadIdx.x & 31;
    int r0 = warp * 2;
    if (r0 >= NN2) return;
    const float4* x0 = (const float4*)(x + (size_t)(1 + NN1 + r0) * CC);
    const float4* x1 = (const float4*)(x + (size_t)(2 + NN1 + r0) * CC);
    const float4* wr = (const float4*)w2;
    float4 a0[4], a1[4];
#pragma unroll
    for (int k = 0; k < 4; k++) a0[k] = x0[lane + 32 * k];
#pragma unroll
    for (int k = 0; k < 4; k++) a1[k] = x1[lane + 32 * k];
    float s0 = 0.f, s1 = 0.f, wsum = 0.f;
#pragma unroll
    for (int k = 0; k < 4; k++) {
        float4 b = wr[lane + 32 * k];
        s0 += a0[k].x * b.x + a0[k].y * b.y + a0[k].z * b.z + a0[k].w * b.w;
        s1 += a1[k].x * b.x + a1[k].y * b.y + a1[k].z * b.z + a1[k].w * b.w;
        wsum += b.x * b.x + b.y * b.y + b.z * b.z + b.w * b.w;
    }
    for (int off = 16; off; off >>= 1) {
        s0   += __shfl_xor_sync(0xffffffffu, s0, off);
        s1   += __shfl_xor_sync(0xffffffffu, s1, off);
        wsum += __shfl_xor_sync(0xffffffffu, wsum, off);
    }
    if (lane == 0) {
        float nrm = sqrtf(wsum);
        g_f2[r0]     = tanhf(s0 / nrm);
        g_f2[r0 + 1] = tanhf(s1 / nrm);
    }
}

// brute-force stable rank of f1 (composite u64 keys)
__global__ void rank_kernel() {
    dep_sync();
    __shared__ unsigned long long sk[1024];
    int jbase = (blockIdx.x & 7) * 1024;
    int i = (blockIdx.x >> 3) * 256 + threadIdx.x;
    for (int k = threadIdx.x; k < 1024; k += 256) {
        int j = jbase + k;
        sk[k] = ((unsigned long long)f2ord(g_f1[j]) << 32) | (unsigned)j;
    }
    __syncthreads();
    unsigned long long ki = ((unsigned long long)f2ord(g_f1[i]) << 32) | (unsigned)i;
    int c = 0;
#pragma unroll 8
    for (int k = 0; k < 1024; k++) c += (sk[k] < ki) ? 1 : 0;
    atomicAdd(&g_rank[i], c);
}

// rank % 10 == 0 -> threshold slot rank/10
__global__ void thr_kernel(const float* __restrict__ xy) {
    dep_sync();
    int i = blockIdx.x * blockDim.x + threadIdx.x;
    if (i >= NN1) return;
    int r = g_rank[i];
    if (r % 10 == 0) {
        int s = r / 10;
        g_thr[s * 3 + 0] = xy[(size_t)(1 + i) * 2];
        g_thr[s * 3 + 1] = xy[(size_t)(1 + i) * 2 + 1];
        g_thr[s * 3 + 2] = g_f1[i];
    }
}

// cluster_1: warp per node, lexicographic (d, t) first-min; fused countsM
__global__ void cluster1_kernel(const float* __restrict__ xy) {
    dep_sync();
    __shared__ float sx[KK1], sy[KK1], sf[KK1];
    for (int k = threadIdx.x; k < KK1; k += blockDim.x) {
        sx[k] = g_thr[k * 3 + 0];
        sy[k] = g_thr[k * 3 + 1];
        sf[k] = g_thr[k * 3 + 2];
    }
    __syncthreads();
    int node = blockIdx.x * 8 + (threadIdx.x >> 5);
    int lane = threadIdx.x & 31;
    if (node >= NN1) return;
    float xj = xy[(size_t)(1 + node) * 2];
    float yj = xy[(size_t)(1 + node) * 2 + 1];
    float fj = g_f1[node];
    float best = INFINITY;
    int bt = KK1;
    for (int t = lane; t < KK1; t += 32) {
        float dx = sx[t] - xj, dy = sy[t] - yj;
        float d = sqrtf(dx * dx + dy * dy) + fabsf(sf[t] - fj);
        if (d < best) { best = d; bt = t; }
    }
    for (int off = 16; off; off >>= 1) {
        float ob = __shfl_xor_sync(0xffffffffu, best, off);
        int   ot = __shfl_xor_sync(0xffffffffu, bt, off);
        if (ob < best || (ob == best && ot < bt)) { best = ob; bt = ot; }
    }
    if (lane == 0) {
        g_cluster1[node] = bt;
        g_cluster[1 + node] = bt + 1;
        atomicAdd(&g_countsM[bt + 1], 1);
    }
}

// parents: 4 elements per thread (MLP=4)
__global__ void parents_kernel(const int* __restrict__ tree) {
    dep_sync();
    int base = (blockIdx.x * blockDim.x + threadIdx.x) * 4;
    if (base >= NN2) return;
    int mt = g_minTree;
    int t0 = tree[1 + NN1 + base];
    int t1 = tree[1 + NN1 + base + 1];
    int t2 = tree[1 + NN1 + base + 2];
    int t3 = tree[1 + NN1 + base + 3];
    int p0 = g_cluster1[t0 - mt];
    int p1 = g_cluster1[t1 - mt];
    int p2 = g_cluster1[t2 - mt];
    int p3 = g_cluster1[t3 - mt];
    *(int4*)(g_parents + base) = make_int4(p0, p1, p2, p3);
    atomicAdd(&g_counts1[p0], 1);
    atomicAdd(&g_counts1[p1], 1);
    atomicAdd(&g_counts1[p2], 1);
    atomicAdd(&g_counts1[p3], 1);
}

// single-block exclusive scan over device symbols (which=0: counts1->starts1; 1: countsM->startsM)
__global__ void scan_kernel(int which) {
    dep_sync();
    __shared__ int sh[256];
    const int* in = which ? g_countsM : g_counts1;
    int* out = which ? g_startsM : g_starts1;
    int n = which ? MM : KK1;
    const int PER = 17;
    int t = threadIdx.x;
    int base = t * PER;
    int loc[PER];
    int s = 0;
#pragma unroll
    for (int i = 0; i < PER; i++) {
        int v = (base + i < n) ? in[base + i] : 0;
        loc[i] = s; s += v;
    }
    sh[t] = s;
    __syncthreads();
    for (int off = 1; off < 256; off <<= 1) {
        int a = (t >= off) ? sh[t - off] : 0;
        __syncthreads();
        sh[t] += a;
        __syncthreads();
    }
    int prev = (t > 0) ? sh[t - 1] : 0;
#pragma unroll
    for (int i = 0; i < PER; i++)
        if (base + i < n) out[base + i] = prev + loc[i];
}

// scatter members: 4 per thread; bump starts1 (consumers recover start = starts1 - cnt)
__global__ void scatter1_kernel() {
    dep_sync();
    int base = (blockIdx.x * blockDim.x + threadIdx.x) * 4;
    if (base >= NN2) return;
    int4 p = *(const int4*)(g_parents + base);
    int q0 = atomicAdd(&g_starts1[p.x], 1);
    int q1 = atomicAdd(&g_starts1[p.y], 1);
    int q2 = atomicAdd(&g_starts1[p.z], 1);
    int q3 = atomicAdd(&g_starts1[p.w], 1);
    g_gmembers[q0] = base;
    g_gmembers[q1] = base + 1;
    g_gmembers[q2] = base + 2;
    g_gmembers[q3] = base + 3;
}

// warp-per-group: top-4 smallest (comp_key, idx) [stable], THEN assign cluster_2
// to this group's members in the same kernel (replaces the cluster2 pass).
__global__ void top4_assign_kernel(const float* __restrict__ xy) {
    dep_sync();
    int g = (blockIdx.x * blockDim.x + threadIdx.x) >> 5;
    int lane = threadIdx.x & 31;
    if (g >= KK1) return;
    int cnt = g_counts1[g];
    int start = g_starts1[g] - cnt;
    const unsigned long long SENT = 0xFFFFFFFFFFFFFFFFull;
    unsigned long long best[4] = {SENT, SENT, SENT, SENT};
    float p4 = 4.0f * (float)g;
    for (int k = lane; k < cnt; k += 32) {
        int i = g_gmembers[start + k];
        float key = p4 + g_f2[i];
        unsigned long long v = ((unsigned long long)f2ord(key) << 32) | (unsigned)i;
        if (v < best[3]) {
            if (v < best[0]) { best[3]=best[2]; best[2]=best[1]; best[1]=best[0]; best[0]=v; }
            else if (v < best[1]) { best[3]=best[2]; best[2]=best[1]; best[1]=v; }
            else if (v < best[2]) { best[3]=best[2]; best[2]=v; }
            else best[3]=v;
        }
    }
    // warp-collective selection of 4 global minima; broadcast cand xyf to all lanes
    float cx[4], cy[4], cf[4];
    bool cvalid[4];
    int ptr = 0;
    for (int r = 0; r < 4; r++) {
        unsigned long long v = (ptr < 4) ? best[ptr] : SENT;
        unsigned long long m = v;
        for (int off = 16; off; off >>= 1) {
            unsigned long long o = __shfl_xor_sync(0xffffffffu, m, off);
            if (o < m) m = o;
        }
        unsigned ball = __ballot_sync(0xffffffffu, (ptr < 4) && (v == m));
        if (ball) { int src = __ffs(ball) - 1; if (lane == src) ptr++; }
        cvalid[r] = (m != SENT);
        if (cvalid[r]) {
            int idx = (int)(unsigned)(m & 0xffffffffULL);
            // every lane loads cand data (broadcast-friendly: same address warp-wide)
            cx[r] = xy[(size_t)(1 + NN1 + idx) * 2];
            cy[r] = xy[(size_t)(1 + NN1 + idx) * 2 + 1];
            cf[r] = g_f2[idx];
        } else {
            cx[r] = 0.f; cy[r] = 0.f; cf[r] = 0.f;
        }
    }
    // assign cluster_2 to this group's members (first-min over r semantics)
    for (int k = lane; k < cnt; k += 32) {
        int i = g_gmembers[start + k];
        float xi = xy[(size_t)(1 + NN1 + i) * 2];
        float yi = xy[(size_t)(1 + NN1 + i) * 2 + 1];
        float fi = g_f2[i];
        float bd = INFINITY;
        int loc = 0;
#pragma unroll
        for (int r = 0; r < 4; r++) {
            if (cvalid[r]) {
                float dx = cx[r] - xi, dy = cy[r] - yi;
                float d = sqrtf(dx * dx + dy * dy) + fabsf(cf[r] - fi);
                if (d < bd) { bd = d; loc = r; }
            }
        }
        int c = g * 4 + loc + 1 + KK1;
        g_cluster[1 + NN1 + i] = c;
        atomicAdd(&g_countsM[c], 1);
    }
}

// scatter nodes: 4 per thread (bump startsM)
__global__ void scatterM_kernel() {
    dep_sync();
    int base = (blockIdx.x * blockDim.x + threadIdx.x) * 4;
    if (base >= NTOT) return;
    int c0 = g_cluster[base];
    int c1 = (base + 1 < NTOT) ? g_cluster[base + 1] : -1;
    int c2 = (base + 2 < NTOT) ? g_cluster[base + 2] : -1;
    int c3 = (base + 3 < NTOT) ? g_cluster[base + 3] : -1;
    int q0 = atomicAdd(&g_startsM[c0], 1);
    g_cmembers[q0] = base;
    if (c1 >= 0) { int q = atomicAdd(&g_startsM[c1], 1); g_cmembers[q] = base + 1; }
    if (c2 >= 0) { int q = atomicAdd(&g_startsM[c2], 1); g_cmembers[q] = base + 2; }
    if (c3 >= 0) { int q = atomicAdd(&g_startsM[c3], 1); g_cmembers[q] = base + 3; }
}

// one block per cluster; 128 threads, float4 per thread; unroll 8
__global__ void pool_kernel(const float* __restrict__ x, const float* __restrict__ xy,
                            float* __restrict__ out) {
    dep_sync();
    int m = blockIdx.x;
    int t = threadIdx.x;
    int cnt = g_countsM[m];
    int start = g_startsM[m] - cnt;
    float4 acc = make_float4(0.f, 0.f, 0.f, 0.f);
    int k = 0;
    for (; k + 8 <= cnt; k += 8) {
        int n0 = g_cmembers[start + k];
        int n1 = g_cmembers[start + k + 1];
        int n2 = g_cmembers[start + k + 2];
        int n3 = g_cmembers[start + k + 3];
        int n4 = g_cmembers[start + k + 4];
        int n5 = g_cmembers[start + k + 5];
        int n6 = g_cmembers[start + k + 6];
        int n7 = g_cmembers[start + k + 7];
        float4 a0 = ((const float4*)(x + (size_t)n0 * CC))[t];
        float4 a1 = ((const float4*)(x + (size_t)n1 * CC))[t];
        float4 a2 = ((const float4*)(x + (size_t)n2 * CC))[t];
        float4 a3 = ((const float4*)(x + (size_t)n3 * CC))[t];
        float4 a4 = ((const float4*)(x + (size_t)n4 * CC))[t];
        float4 a5 = ((const float4*)(x + (size_t)n5 * CC))[t];
        float4 a6 = ((const float4*)(x + (size_t)n6 * CC))[t];
        float4 a7 = ((const float4*)(x + (size_t)n7 * CC))[t];
        acc.x += (a0.x + a1.x) + (a2.x + a3.x) + ((a4.x + a5.x) + (a6.x + a7.x));
        acc.y += (a0.y + a1.y) + (a2.y + a3.y) + ((a4.y + a5.y) + (a6.y + a7.y));
        acc.z += (a0.z + a1.z) + (a2.z + a3.z) + ((a4.z + a5.z) + (a6.z + a7.z));
        acc.w += (a0.w + a1.w) + (a2.w + a3.w) + ((a4.w + a5.w) + (a6.w + a7.w));
    }
    for (; k < cnt; k++) {
        float4 a = ((const float4*)(x + (size_t)g_cmembers[start + k] * CC))[t];
        acc.x += a.x; acc.y += a.y; acc.z += a.z; acc.w += a.w;
    }
    float inv = 1.0f / (float)(cnt > 0 ? cnt : 1);
    acc.x *= inv; acc.y *= inv; acc.z *= inv; acc.w *= inv;
    ((float4*)(out + OFF_XPOOL + (size_t)m * CC))[t] = acc;
    if (t < 32) {
        float ax = 0.f, ay = 0.f;
        for (int kk = t; kk < cnt; kk += 32) {
            int node = g_cmembers[start + kk];
            ax += xy[(size_t)node * 2];
            ay += xy[(size_t)node * 2 + 1];
        }
        for (int off = 16; off; off >>= 1) {
            ax += __shfl_xor_sync(0xffffffffu, ax, off);
            ay += __shfl_xor_sync(0xffffffffu, ay, off);
        }
        if (t == 0) {
            out[OFF_NEWXY + (size_t)m * 2]     = ax * inv;
            out[OFF_NEWXY + (size_t)m * 2 + 1] = ay * inv;
        }
    }
}

// edge accumulation (int4-vectorized) + fused tail outputs
__global__ void edge_tail_kernel(const int* __restrict__ ei, float* __restrict__ out) {
    int gsz = gridDim.x * blockDim.x;
    int gid = blockIdx.x * blockDim.x + threadIdx.x;
    for (int i = gid; i < NTOT; i += gsz) {
        out[OFF_CLUST + i] = (float)g_cluster[i];
        float fit;
        if (i == 0) fit = 0.f;
        else if (i <= NN1) fit = g_f1[i - 1];
        else fit = g_f2[i - 1 - NN1];
        out[OFF_FIT + i] = fit;
        if (i < MM) {
            out[OFF_BATCH + i] = 0.f;
            out[OFF_NNT + i] = (i == 0) ? 0.f : ((i <= KK1) ? 1.f : 2.f);
            out[OFF_NTREE + i] = (i == 0) ? -1.f : ((i <= KK1) ? 0.f : (float)((i - 1 - KK1) / 4 + 1));
            atomicAdd(&out[OFF_A + (size_t)i * MM + i], (float)g_countsM[i]);
        }
    }
    for (int e4 = gid; e4 < EE / 4; e4 += gsz) {
        int4 rr = ((const int4*)ei)[e4];
        int4 cc = ((const int4*)(ei + EE))[e4];
        int r0 = g_cluster[rr.x], r1 = g_cluster[rr.y], r2 = g_cluster[rr.z], r3 = g_cluster[rr.w];
        int c0 = g_cluster[cc.x], c1 = g_cluster[cc.y], c2 = g_cluster[cc.z], c3 = g_cluster[cc.w];
        atomicAdd(&out[OFF_A + (size_t)r0 * MM + c0], 1.0f);
        atomicAdd(&out[OFF_A + (size_t)r1 * MM + c1], 1.0f);
        atomicAdd(&out[OFF_A + (size_t)r2 * MM + c2], 1.0f);
        atomicAdd(&out[OFF_A + (size_t)r3 * MM + c3], 1.0f);
    }
}

// ---------------- PDL launch helper ----------------
template <typename... Args>
static void launch_pdl(void (*kern)(Args...), dim3 grid, dim3 block, cudaStream_t s,
                       Args... args) {
    cudaLaunchConfig_t cfg = {};
    cfg.gridDim = grid;
    cfg.blockDim = block;
    cfg.stream = s;
    cudaLaunchAttribute at[1];
    at[0].id = cudaLaunchAttributeProgrammaticStreamSerialization;
    at[0].val.programmaticStreamSerializationAllowed = 1;
    cfg.attrs = at;
    cfg.numAttrs = 1;
    cudaLaunchKernelEx(&cfg, kern, args...);
}

// ---------------- launch ----------------
extern "C" void kernel_launch(void* const* d_in, const int* in_sizes, int n_in,
                              void* d_out, int out_size) {
    const float* x    = (const float*)d_in[0];
    const int*   ei   = (const int*)d_in[1];
    const int*   tree = (const int*)d_in[3];
    const float* xy   = (const float*)d_in[4];
    const float* w1   = (const float*)d_in[5];
    const float* w2   = (const float*)d_in[6];
    float* out = (float*)d_out;

    static cudaStream_t s1 = nullptr, s2 = nullptr;
    static cudaEvent_t e0 = nullptr, eMs = nullptr, eS1 = nullptr, eC2 = nullptr, eS1b = nullptr;
    if (!s1) {
        cudaStreamCreateWithFlags(&s1, cudaStreamNonBlocking);
        cudaStreamCreateWithFlags(&s2, cudaStreamNonBlocking);
        cudaEventCreateWithFlags(&e0, cudaEventDisableTiming);
        cudaEventCreateWithFlags(&eMs, cudaEventDisableTiming);
        cudaEventCreateWithFlags(&eS1, cudaEventDisableTiming);
        cudaEventCreateWithFlags(&eC2, cudaEventDisableTiming);
        cudaEventCreateWithFlags(&eS1b, cudaEventDisableTiming);
    }

    cudaEventRecord(e0, 0);
    cudaStreamWaitEvent(s1, e0, 0);
    cudaStreamWaitEvent(s2, e0, 0);

    // s2: A memset (needed only by edge/tail)
    cudaMemsetAsync(out + OFF_A, 0, (size_t)MM * MM * sizeof(float), s2);
    cudaEventRecord(eMs, s2);

    // s1: f1-dependent chain, PDL-linked, hidden under f2's bandwidth sweep
    f1_kernel<<<512, 256, 0, s1>>>(x, w1, tree);
    launch_pdl(rank_kernel, dim3(256), dim3(256), s1);
    launch_pdl(thr_kernel, dim3(32), dim3(256), s1, xy);
    launch_pdl(cluster1_kernel, dim3(NN1 / 8), dim3(256), s1, xy);
    launch_pdl(parents_kernel, dim3(NN2 / 1024), dim3(256), s1, tree);
    launch_pdl(scan_kernel, dim3(1), dim3(256), s1, 0);
    launch_pdl(scatter1_kernel, dim3(NN2 / 1024), dim3(256), s1);
    cudaEventRecord(eS1, s1);

    // s0: the big f2 sweep (2 rows per warp)
    f2_kernel<<<NN2 * 16 / 256, 256>>>(x, w2);

    // join: top4+assign needs f2 + scatter1
    cudaStreamWaitEvent(0, eS1, 0);
    launch_pdl(top4_assign_kernel, dim3((KK1 * 32 + 255) / 256), dim3(256), (cudaStream_t)0, xy);
    cudaEventRecord(eC2, 0);

    // s1: edge + tail (need cluster complete + memset), concurrent with scan/scatter/pool
    cudaStreamWaitEvent(s1, eC2, 0);
    cudaStreamWaitEvent(s1, eMs, 0);
    edge_tail_kernel<<<1024, 256, 0, s1>>>(ei, out);
    cudaEventRecord(eS1b, s1);

    // s0: scanM -> scatterM -> pool, PDL-linked
    launch_pdl(scan_kernel, dim3(1), dim3(256), (cudaStream_t)0, 1);
    launch_pdl(scatterM_kernel, dim3((NTOT + 1023) / 1024), dim3(256), (cudaStream_t)0);
    launch_pdl(pool_kernel, dim3(MM), dim3(128), (cudaStream_t)0, x, xy, out);
    cudaStreamWaitEvent(0, eS1b, 0);
}

// round 14
// speedup vs baseline: 1.0924x; 1.0924x over previous
#include <cuda_runtime.h>
#include <math.h>
#include <stdint.h>

#define CC   512
#define NN1  8192
#define NN2  131072
#define NTOT 139265
#define EE   1000000
#define KK1  820
#define KK2  3280
#define MM   4101

// output layout (float32, tuple concatenated)
#define OFF_XPOOL 0ULL
#define OFF_A     2099712ULL
#define OFF_BATCH 18917913ULL
#define OFF_CLUST 18922014ULL
#define OFF_NNT   19061279ULL
#define OFF_NTREE 19065380ULL
#define OFF_FIT   19069481ULL
#define OFF_NEWXY 19208746ULL

// ---------------- device scratch ----------------
__device__ float g_f1[NN1];
__device__ float g_f2[NN2];
__device__ int   g_rank[NN1];
__device__ float g_thr[KK1 * 3];
__device__ int   g_cluster1[NN1];
__device__ int   g_parents[NN2];
__device__ int   g_counts1[KK1];
__device__ int   g_starts1[KK1];
__device__ int   g_gmembers[NN2];
__device__ int   g_cluster[NTOT];
__device__ int   g_countsM[MM];
__device__ int   g_startsM[MM];
__device__ int   g_cmembers[NTOT];
__device__ int   g_minTree = 0x7fffffff;   // persistent: atomicMin idempotent across replays

__device__ __forceinline__ unsigned int f2ord(float f) {
    unsigned int u = __float_as_uint(f);
    return (u & 0x80000000u) ? ~u : (u | 0x80000000u);
}

__device__ __forceinline__ void dep_sync() {
#if __CUDA_ARCH__ >= 900
    cudaGridDependencySynchronize();
#endif
}

// ---------------- f1: 8192 fitness rows (2 rows/warp, streaming x) + zero counters + tree-min
__global__ void f1_kernel(const float* __restrict__ x,
                          const float* __restrict__ w1,
                          const int* __restrict__ tree) {
    int gid = blockIdx.x * blockDim.x + threadIdx.x;   // 512 blocks * 256
    if (gid < NN1) g_rank[gid] = 0;
    if (gid < KK1) g_counts1[gid] = 0;
    if (gid < MM)  g_countsM[gid] = (gid == 0) ? 1 : 0;
    if (gid == 0)  g_cluster[0] = 0;
    if (blockIdx.x < 64) {
        __shared__ int smin[256];
        int v = 0x7fffffff;
        for (int i = blockIdx.x * 256 + threadIdx.x; i < NN2; i += 64 * 256)
            v = min(v, tree[1 + NN1 + i]);
        smin[threadIdx.x] = v;
        __syncthreads();
        for (int off = 128; off; off >>= 1) {
            if (threadIdx.x < off) smin[threadIdx.x] = min(smin[threadIdx.x], smin[threadIdx.x + off]);
            __syncthreads();
        }
        if (threadIdx.x == 0) atomicMin(&g_minTree, smin[0]);
        __syncthreads();
    }
    int warp = gid >> 5;
    int lane = threadIdx.x & 31;
    int r0 = warp * 2;
    if (r0 >= NN1) return;
    const float4* x0 = (const float4*)(x + (size_t)(1 + r0) * CC);
    const float4* x1 = (const float4*)(x + (size_t)(2 + r0) * CC);
    const float4* wr = (const float4*)w1;
    float4 a0[4], a1[4];
#pragma unroll
    for (int k = 0; k < 4; k++) a0[k] = __ldcs(x0 + lane + 32 * k);
#pragma unroll
    for (int k = 0; k < 4; k++) a1[k] = __ldcs(x1 + lane + 32 * k);
    float s0 = 0.f, s1 = 0.f, wsum = 0.f;
#pragma unroll
    for (int k = 0; k < 4; k++) {
        float4 b = wr[lane + 32 * k];
        s0 += a0[k].x * b.x + a0[k].y * b.y + a0[k].z * b.z + a0[k].w * b.w;
        s1 += a1[k].x * b.x + a1[k].y * b.y + a1[k].z * b.z + a1[k].w * b.w;
        wsum += b.x * b.x + b.y * b.y + b.z * b.z + b.w * b.w;
    }
    for (int off = 16; off; off >>= 1) {
        s0   += __shfl_xor_sync(0xffffffffu, s0, off);
        s1   += __shfl_xor_sync(0xffffffffu, s1, off);
        wsum += __shfl_xor_sync(0xffffffffu, wsum, off);
    }
    if (lane == 0) {
        float nrm = sqrtf(wsum);
        g_f1[r0]     = tanhf(s0 / nrm);
        g_f1[r0 + 1] = tanhf(s1 / nrm);
    }
}

// ---------------- f2: 131072 fitness rows, 2 rows per warp, streaming x
__global__ void f2_kernel(const float* __restrict__ x, const float* __restrict__ w2) {
    int warp = (blockIdx.x * blockDim.x + threadIdx.x) >> 5;
    int lane = threadIdx.x & 31;
    int r0 = warp * 2;
    if (r0 >= NN2) return;
    const float4* x0 = (const float4*)(x + (size_t)(1 + NN1 + r0) * CC);
    const float4* x1 = (const float4*)(x + (size_t)(2 + NN1 + r0) * CC);
    const float4* wr = (const float4*)w2;
    float4 a0[4], a1[4];
#pragma unroll
    for (int k = 0; k < 4; k++) a0[k] = __ldcs(x0 + lane + 32 * k);
#pragma unroll
    for (int k = 0; k < 4; k++) a1[k] = __ldcs(x1 + lane + 32 * k);
    float s0 = 0.f, s1 = 0.f, wsum = 0.f;
#pragma unroll
    for (int k = 0; k < 4; k++) {
        float4 b = wr[lane + 32 * k];
        s0 += a0[k].x * b.x + a0[k].y * b.y + a0[k].z * b.z + a0[k].w * b.w;
        s1 += a1[k].x * b.x + a1[k].y * b.y + a1[k].z * b.z + a1[k].w * b.w;
        wsum += b.x * b.x + b.y * b.y + b.z * b.z + b.w * b.w;
    }
    for (int off = 16; off; off >>= 1) {
        s0   += __shfl_xor_sync(0xffffffffu, s0, off);
        s1   += __shfl_xor_sync(0xffffffffu, s1, off);
        wsum += __shfl_xor_sync(0xffffffffu, wsum, off);
    }
    if (lane == 0) {
        float nrm = sqrtf(wsum);
        g_f2[r0]     = tanhf(s0 / nrm);
        g_f2[r0 + 1] = tanhf(s1 / nrm);
    }
}

// brute-force stable rank of f1 (composite u64 keys)
__global__ void rank_kernel() {
    dep_sync();
    __shared__ unsigned long long sk[1024];
    int jbase = (blockIdx.x & 7) * 1024;
    int i = (blockIdx.x >> 3) * 256 + threadIdx.x;
    for (int k = threadIdx.x; k < 1024; k += 256) {
        int j = jbase + k;
        sk[k] = ((unsigned long long)f2ord(g_f1[j]) << 32) | (unsigned)j;
    }
    __syncthreads();
    unsigned long long ki = ((unsigned long long)f2ord(g_f1[i]) << 32) | (unsigned)i;
    int c = 0;
#pragma unroll 8
    for (int k = 0; k < 1024; k++) c += (sk[k] < ki) ? 1 : 0;
    atomicAdd(&g_rank[i], c);
}

// rank % 10 == 0 -> threshold slot rank/10
__global__ void thr_kernel(const float* __restrict__ xy) {
    dep_sync();
    int i = blockIdx.x * blockDim.x + threadIdx.x;
    if (i >= NN1) return;
    int r = g_rank[i];
    if (r % 10 == 0) {
        int s = r / 10;
        g_thr[s * 3 + 0] = xy[(size_t)(1 + i) * 2];
        g_thr[s * 3 + 1] = xy[(size_t)(1 + i) * 2 + 1];
        g_thr[s * 3 + 2] = g_f1[i];
    }
}

// cluster_1: warp per node, lexicographic (d, t) first-min; fused countsM
__global__ void cluster1_kernel(const float* __restrict__ xy) {
    dep_sync();
    __shared__ float sx[KK1], sy[KK1], sf[KK1];
    for (int k = threadIdx.x; k < KK1; k += blockDim.x) {
        sx[k] = g_thr[k * 3 + 0];
        sy[k] = g_thr[k * 3 + 1];
        sf[k] = g_thr[k * 3 + 2];
    }
    __syncthreads();
    int node = blockIdx.x * 8 + (threadIdx.x >> 5);
    int lane = threadIdx.x & 31;
    if (node >= NN1) return;
    float xj = xy[(size_t)(1 + node) * 2];
    float yj = xy[(size_t)(1 + node) * 2 + 1];
    float fj = g_f1[node];
    float best = INFINITY;
    int bt = KK1;
    for (int t = lane; t < KK1; t += 32) {
        float dx = sx[t] - xj, dy = sy[t] - yj;
        float d = sqrtf(dx * dx + dy * dy) + fabsf(sf[t] - fj);
        if (d < best) { best = d; bt = t; }
    }
    for (int off = 16; off; off >>= 1) {
        float ob = __shfl_xor_sync(0xffffffffu, best, off);
        int   ot = __shfl_xor_sync(0xffffffffu, bt, off);
        if (ob < best || (ob == best && ot < bt)) { best = ob; bt = ot; }
    }
    if (lane == 0) {
        g_cluster1[node] = bt;
        g_cluster[1 + node] = bt + 1;
        atomicAdd(&g_countsM[bt + 1], 1);
    }
}

// parents: 4 elements per thread (MLP=4)
__global__ void parents_kernel(const int* __restrict__ tree) {
    dep_sync();
    int base = (blockIdx.x * blockDim.x + threadIdx.x) * 4;
    if (base >= NN2) return;
    int mt = g_minTree;
    int t0 = tree[1 + NN1 + base];
    int t1 = tree[1 + NN1 + base + 1];
    int t2 = tree[1 + NN1 + base + 2];
    int t3 = tree[1 + NN1 + base + 3];
    int p0 = g_cluster1[t0 - mt];
    int p1 = g_cluster1[t1 - mt];
    int p2 = g_cluster1[t2 - mt];
    int p3 = g_cluster1[t3 - mt];
    *(int4*)(g_parents + base) = make_int4(p0, p1, p2, p3);
    atomicAdd(&g_counts1[p0], 1);
    atomicAdd(&g_counts1[p1], 1);
    atomicAdd(&g_counts1[p2], 1);
    atomicAdd(&g_counts1[p3], 1);
}

// single-block exclusive scan over device symbols (which=0: counts1->starts1; 1: countsM->startsM)
__global__ void scan_kernel(int which) {
    dep_sync();
    __shared__ int sh[256];
    const int* in = which ? g_countsM : g_counts1;
    int* out = which ? g_startsM : g_starts1;
    int n = which ? MM : KK1;
    const int PER = 17;
    int t = threadIdx.x;
    int base = t * PER;
    int loc[PER];
    int s = 0;
#pragma unroll
    for (int i = 0; i < PER; i++) {
        int v = (base + i < n) ? in[base + i] : 0;
        loc[i] = s; s += v;
    }
    sh[t] = s;
    __syncthreads();
    for (int off = 1; off < 256; off <<= 1) {
        int a = (t >= off) ? sh[t - off] : 0;
        __syncthreads();
        sh[t] += a;
        __syncthreads();
    }
    int prev = (t > 0) ? sh[t - 1] : 0;
#pragma unroll
    for (int i = 0; i < PER; i++)
        if (base + i < n) out[base + i] = prev + loc[i];
}

// scatter members: 4 per thread; bump starts1 (consumers recover start = starts1 - cnt)
__global__ void scatter1_kernel() {
    dep_sync();
    int base = (blockIdx.x * blockDim.x + threadIdx.x) * 4;
    if (base >= NN2) return;
    int4 p = *(const int4*)(g_parents + base);
    int q0 = atomicAdd(&g_starts1[p.x], 1);
    int q1 = atomicAdd(&g_starts1[p.y], 1);
    int q2 = atomicAdd(&g_starts1[p.z], 1);
    int q3 = atomicAdd(&g_starts1[p.w], 1);
    g_gmembers[q0] = base;
    g_gmembers[q1] = base + 1;
    g_gmembers[q2] = base + 2;
    g_gmembers[q3] = base + 3;
}

// warp-per-group: top-4 smallest (comp_key, idx) [stable], then assign cluster_2
__global__ void top4_assign_kernel(const float* __restrict__ xy) {
    dep_sync();
    int g = (blockIdx.x * blockDim.x + threadIdx.x) >> 5;
    int lane = threadIdx.x & 31;
    if (g >= KK1) return;
    int cnt = g_counts1[g];
    int start = g_starts1[g] - cnt;
    const unsigned long long SENT = 0xFFFFFFFFFFFFFFFFull;
    unsigned long long best[4] = {SENT, SENT, SENT, SENT};
    float p4 = 4.0f * (float)g;
    for (int k = lane; k < cnt; k += 32) {
        int i = g_gmembers[start + k];
        float key = p4 + g_f2[i];
        unsigned long long v = ((unsigned long long)f2ord(key) << 32) | (unsigned)i;
        if (v < best[3]) {
            if (v < best[0]) { best[3]=best[2]; best[2]=best[1]; best[1]=best[0]; best[0]=v; }
            else if (v < best[1]) { best[3]=best[2]; best[2]=best[1]; best[1]=v; }
            else if (v < best[2]) { best[3]=best[2]; best[2]=v; }
            else best[3]=v;
        }
    }
    float cx[4], cy[4], cf[4];
    bool cvalid[4];
    int ptr = 0;
    for (int r = 0; r < 4; r++) {
        unsigned long long v = (ptr < 4) ? best[ptr] : SENT;
        unsigned long long m = v;
        for (int off = 16; off; off >>= 1) {
            unsigned long long o = __shfl_xor_sync(0xffffffffu, m, off);
            if (o < m) m = o;
        }
        unsigned ball = __ballot_sync(0xffffffffu, (ptr < 4) && (v == m));
        if (ball) { int src = __ffs(ball) - 1; if (lane == src) ptr++; }
        cvalid[r] = (m != SENT);
        if (cvalid[r]) {
            int idx = (int)(unsigned)(m & 0xffffffffULL);
            cx[r] = xy[(size_t)(1 + NN1 + idx) * 2];
            cy[r] = xy[(size_t)(1 + NN1 + idx) * 2 + 1];
            cf[r] = g_f2[idx];
        } else {
            cx[r] = 0.f; cy[r] = 0.f; cf[r] = 0.f;
        }
    }
    for (int k = lane; k < cnt; k += 32) {
        int i = g_gmembers[start + k];
        float xi = xy[(size_t)(1 + NN1 + i) * 2];
        float yi = xy[(size_t)(1 + NN1 + i) * 2 + 1];
        float fi = g_f2[i];
        float bd = INFINITY;
        int loc = 0;
#pragma unroll
        for (int r = 0; r < 4; r++) {
            if (cvalid[r]) {
                float dx = cx[r] - xi, dy = cy[r] - yi;
                float d = sqrtf(dx * dx + dy * dy) + fabsf(cf[r] - fi);
                if (d < bd) { bd = d; loc = r; }
            }
        }
        int c = g * 4 + loc + 1 + KK1;
        g_cluster[1 + NN1 + i] = c;
        atomicAdd(&g_countsM[c], 1);
    }
}

// scatter nodes: 4 per thread (bump startsM)
__global__ void scatterM_kernel() {
    dep_sync();
    int base = (blockIdx.x * blockDim.x + threadIdx.x) * 4;
    if (base >= NTOT) return;
    int c0 = g_cluster[base];
    int c1 = (base + 1 < NTOT) ? g_cluster[base + 1] : -1;
    int c2 = (base + 2 < NTOT) ? g_cluster[base + 2] : -1;
    int c3 = (base + 3 < NTOT) ? g_cluster[base + 3] : -1;
    int q0 = atomicAdd(&g_startsM[c0], 1);
    g_cmembers[q0] = base;
    if (c1 >= 0) { int q = atomicAdd(&g_startsM[c1], 1); g_cmembers[q] = base + 1; }
    if (c2 >= 0) { int q = atomicAdd(&g_startsM[c2], 1); g_cmembers[q] = base + 2; }
    if (c3 >= 0) { int q = atomicAdd(&g_startsM[c3], 1); g_cmembers[q] = base + 3; }
}

// one block per cluster; 128 threads, float4 per thread; unroll 8; streaming x
__global__ void pool_kernel(const float* __restrict__ x, const float* __restrict__ xy,
                            float* __restrict__ out) {
    dep_sync();
    int m = blockIdx.x;
    int t = threadIdx.x;
    int cnt = g_countsM[m];
    int start = g_startsM[m] - cnt;
    float4 acc = make_float4(0.f, 0.f, 0.f, 0.f);
    int k = 0;
    for (; k + 8 <= cnt; k += 8) {
        int n0 = g_cmembers[start + k];
        int n1 = g_cmembers[start + k + 1];
        int n2 = g_cmembers[start + k + 2];
        int n3 = g_cmembers[start + k + 3];
        int n4 = g_cmembers[start + k + 4];
        int n5 = g_cmembers[start + k + 5];
        int n6 = g_cmembers[start + k + 6];
        int n7 = g_cmembers[start + k + 7];
        float4 a0 = __ldcs((const float4*)(x + (size_t)n0 * CC) + t);
        float4 a1 = __ldcs((const float4*)(x + (size_t)n1 * CC) + t);
        float4 a2 = __ldcs((const float4*)(x + (size_t)n2 * CC) + t);
        float4 a3 = __ldcs((const float4*)(x + (size_t)n3 * CC) + t);
        float4 a4 = __ldcs((const float4*)(x + (size_t)n4 * CC) + t);
        float4 a5 = __ldcs((const float4*)(x + (size_t)n5 * CC) + t);
        float4 a6 = __ldcs((const float4*)(x + (size_t)n6 * CC) + t);
        float4 a7 = __ldcs((const float4*)(x + (size_t)n7 * CC) + t);
        acc.x += (a0.x + a1.x) + (a2.x + a3.x) + ((a4.x + a5.x) + (a6.x + a7.x));
        acc.y += (a0.y + a1.y) + (a2.y + a3.y) + ((a4.y + a5.y) + (a6.y + a7.y));
        acc.z += (a0.z + a1.z) + (a2.z + a3.z) + ((a4.z + a5.z) + (a6.z + a7.z));
        acc.w += (a0.w + a1.w) + (a2.w + a3.w) + ((a4.w + a5.w) + (a6.w + a7.w));
    }
    for (; k < cnt; k++) {
        float4 a = __ldcs((const float4*)(x + (size_t)g_cmembers[start + k] * CC) + t);
        acc.x += a.x; acc.y += a.y; acc.z += a.z; acc.w += a.w;
    }
    float inv = 1.0f / (float)(cnt > 0 ? cnt : 1);
    acc.x *= inv; acc.y *= inv; acc.z *= inv; acc.w *= inv;
    __stcs((float4*)(out + OFF_XPOOL + (size_t)m * CC) + t, acc);
    if (t < 32) {
        float ax = 0.f, ay = 0.f;
        for (int kk = t; kk < cnt; kk += 32) {
            int node = g_cmembers[start + kk];
            ax += xy[(size_t)node * 2];
            ay += xy[(size_t)node * 2 + 1];
        }
        for (int off = 16; off; off >>= 1) {
            ax += __shfl_xor_sync(0xffffffffu, ax, off);
            ay += __shfl_xor_sync(0xffffffffu, ay, off);
        }
        if (t == 0) {
            out[OFF_NEWXY + (size_t)m * 2]     = ax * inv;
            out[OFF_NEWXY + (size_t)m * 2 + 1] = ay * inv;
        }
    }
}

// edge accumulation (int4-vectorized, streaming ei) + fused tail outputs
__global__ void edge_tail_kernel(const int* __restrict__ ei, float* __restrict__ out) {
    int gsz = gridDim.x * blockDim.x;
    int gid = blockIdx.x * blockDim.x + threadIdx.x;
    for (int i = gid; i < NTOT; i += gsz) {
        out[OFF_CLUST + i] = (float)g_cluster[i];
        float fit;
        if (i == 0) fit = 0.f;
        else if (i <= NN1) fit = g_f1[i - 1];
        else fit = g_f2[i - 1 - NN1];
        out[OFF_FIT + i] = fit;
        if (i < MM) {
            out[OFF_BATCH + i] = 0.f;
            out[OFF_NNT + i] = (i == 0) ? 0.f : ((i <= KK1) ? 1.f : 2.f);
            out[OFF_NTREE + i] = (i == 0) ? -1.f : ((i <= KK1) ? 0.f : (float)((i - 1 - KK1) / 4 + 1));
            atomicAdd(&out[OFF_A + (size_t)i * MM + i], (float)g_countsM[i]);
        }
    }
    for (int e4 = gid; e4 < EE / 4; e4 += gsz) {
        int4 rr = __ldcs((const int4*)ei + e4);
        int4 cc = __ldcs((const int4*)(ei + EE) + e4);
        int r0 = g_cluster[rr.x], r1 = g_cluster[rr.y], r2 = g_cluster[rr.z], r3 = g_cluster[rr.w];
        int c0 = g_cluster[cc.x], c1 = g_cluster[cc.y], c2 = g_cluster[cc.z], c3 = g_cluster[cc.w];
        atomicAdd(&out[OFF_A + (size_t)r0 * MM + c0], 1.0f);
        atomicAdd(&out[OFF_A + (size_t)r1 * MM + c1], 1.0f);
        atomicAdd(&out[OFF_A + (size_t)r2 * MM + c2], 1.0f);
        atomicAdd(&out[OFF_A + (size_t)r3 * MM + c3], 1.0f);
    }
}

// ---------------- PDL launch helper ----------------
template <typename... Args>
static void launch_pdl(void (*kern)(Args...), dim3 grid, dim3 block, cudaStream_t s,
                       Args... args) {
    cudaLaunchConfig_t cfg = {};
    cfg.gridDim = grid;
    cfg.blockDim = block;
    cfg.stream = s;
    cudaLaunchAttribute at[1];
    at[0].id = cudaLaunchAttributeProgrammaticStreamSerialization;
    at[0].val.programmaticStreamSerializationAllowed = 1;
    cfg.attrs = at;
    cfg.numAttrs = 1;
    cudaLaunchKernelEx(&cfg, kern, args...);
}

// ---------------- launch ----------------
extern "C" void kernel_launch(void* const* d_in, const int* in_sizes, int n_in,
                              void* d_out, int out_size) {
    const float* x    = (const float*)d_in[0];
    const int*   ei   = (const int*)d_in[1];
    const int*   tree = (const int*)d_in[3];
    const float* xy   = (const float*)d_in[4];
    const float* w1   = (const float*)d_in[5];
    const float* w2   = (const float*)d_in[6];
    float* out = (float*)d_out;

    static cudaStream_t s1 = nullptr, s2 = nullptr;
    static cudaEvent_t e0 = nullptr, eMs = nullptr, eS1 = nullptr, eC2 = nullptr, eS1b = nullptr;
    if (!s1) {
        cudaStreamCreateWithFlags(&s1, cudaStreamNonBlocking);
        cudaStreamCreateWithFlags(&s2, cudaStreamNonBlocking);
        cudaEventCreateWithFlags(&e0, cudaEventDisableTiming);
        cudaEventCreateWithFlags(&eMs, cudaEventDisableTiming);
        cudaEventCreateWithFlags(&eS1, cudaEventDisableTiming);
        cudaEventCreateWithFlags(&eC2, cudaEventDisableTiming);
        cudaEventCreateWithFlags(&eS1b, cudaEventDisableTiming);
    }

    cudaEventRecord(e0, 0);
    cudaStreamWaitEvent(s1, e0, 0);
    cudaStreamWaitEvent(s2, e0, 0);

    // s2: A memset (A stays L2-resident; x loads are streaming-hinted)
    cudaMemsetAsync(out + OFF_A, 0, (size_t)MM * MM * sizeof(float), s2);
    cudaEventRecord(eMs, s2);

    // s1: f1-dependent chain, PDL-linked, hidden under f2's bandwidth sweep
    f1_kernel<<<512, 256, 0, s1>>>(x, w1, tree);
    launch_pdl(rank_kernel, dim3(256), dim3(256), s1);
    launch_pdl(thr_kernel, dim3(32), dim3(256), s1, xy);
    launch_pdl(cluster1_kernel, dim3(NN1 / 8), dim3(256), s1, xy);
    launch_pdl(parents_kernel, dim3(NN2 / 1024), dim3(256), s1, tree);
    launch_pdl(scan_kernel, dim3(1), dim3(256), s1, 0);
    launch_pdl(scatter1_kernel, dim3(NN2 / 1024), dim3(256), s1);
    cudaEventRecord(eS1, s1);

    // s0: the big f2 sweep (2 rows per warp)
    f2_kernel<<<NN2 * 16 / 256, 256>>>(x, w2);

    // join: top4+assign needs f2 + scatter1
    cudaStreamWaitEvent(0, eS1, 0);
    launch_pdl(top4_assign_kernel, dim3((KK1 * 32 + 255) / 256), dim3(256), (cudaStream_t)0, xy);
    cudaEventRecord(eC2, 0);

    // s1: edge + tail (need cluster complete + memset), concurrent with scan/scatter/pool
    cudaStreamWaitEvent(s1, eC2, 0);
    cudaStreamWaitEvent(s1, eMs, 0);
    edge_tail_kernel<<<1024, 256, 0, s1>>>(ei, out);
    cudaEventRecord(eS1b, s1);

    // s0: scanM -> scatterM -> pool, PDL-linked
    launch_pdl(scan_kernel, dim3(1), dim3(256), (cudaStream_t)0, 1);
    launch_pdl(scatterM_kernel, dim3((NTOT + 1023) / 1024), dim3(256), (cudaStream_t)0);
    launch_pdl(pool_kernel, dim3(MM), dim3(128), (cudaStream_t)0, x, xy, out);
    cudaStreamWaitEvent(0, eS1b, 0);
}